// round 1
// baseline (speedup 1.0000x reference)
#include <cuda_runtime.h>
#include <cuda_bf16.h>
#include <math.h>
#include <cub/cub.cuh>

#define NANCH   331776      // 192*192*9
#define CHUNK   512
#define MAXACC  300
#define NGT     64
#define NMS_THR 0.7f
#define BG_THR  0.5f
#define NUM_CLASSES 20.0f

// ---------------- static device scratch (no runtime allocation) ----------------
__device__ unsigned int g_keys[NANCH];
__device__ unsigned int g_vals[NANCH];
__device__ unsigned int g_keys_s[NANCH];
__device__ unsigned int g_vals_s[NANCH];
__device__ unsigned int g_selPos[MAXACC];
#define CUB_TMP_BYTES (32u << 20)
__device__ unsigned char g_cub_tmp[CUB_TMP_BYTES];

// ---------------- kernel 1: build sortable keys ----------------
// conf in (0.5, 1] -> monotone 24-bit key = float_bits(conf) - 0x3F000000; else 0.
__global__ void build_keys_kernel(const float* __restrict__ confs,
                                  unsigned int* __restrict__ keys,
                                  unsigned int* __restrict__ vals) {
    int i = blockIdx.x * blockDim.x + threadIdx.x;
    if (i < NANCH) {
        float c = confs[i];
        keys[i] = (c > 0.5f) ? (__float_as_uint(c) - 0x3F000000u) : 0u;
        vals[i] = (unsigned int)i;
    }
}

__device__ __forceinline__ float iou_mm(float ax0, float ay0, float ax1, float ay1,
                                        float bx0, float by0, float bx1, float by1) {
    float tlx = fmaxf(ax0, bx0), tly = fmaxf(ay0, by0);
    float brx = fminf(ax1, bx1), bry = fminf(ay1, by1);
    float w = fmaxf(brx - tlx, 0.0f), h = fmaxf(bry - tly, 0.0f);
    float inter = w * h;
    float aa = (ax1 - ax0) * (ay1 - ay0);
    float ab = (bx1 - bx0) * (by1 - by0);
    return inter / (aa + ab - inter + 1e-9f);
}

// ---------------- kernel 2: single-block greedy NMS + outputs ----------------
__global__ __launch_bounds__(CHUNK, 1)
void nms_kernel(const unsigned int* __restrict__ keysS,
                const unsigned int* __restrict__ valsS,
                const float* __restrict__ deltas,
                const float* __restrict__ anchors,
                const float* __restrict__ gt_objs,
                const float* __restrict__ gt_cls,
                float* __restrict__ out) {
    __shared__ float4 sBox[CHUNK];                       // decoded xymm per chunk candidate
    __shared__ unsigned char sValid[CHUNK];              // candidate & survived pre-filter
    __shared__ unsigned long long sMask[CHUNK][CHUNK/64];// triangular suppression bits
    __shared__ float4 sAccBox[MAXACC];                   // accepted boxes (xymm)
    __shared__ float4 sGt[NGT];                          // GT boxes (xymm)
    __shared__ float  sGtCls[NGT];
    __shared__ int    sNAcc;
    __shared__ int    sStop;

    const int tid = threadIdx.x;
    if (tid == 0) sNAcc = 0;
    // preload GT boxes (needed only at the end, but load early/once)
    if (tid < NGT) {
        float gx = gt_objs[tid*4+0], gy = gt_objs[tid*4+1];
        float gw = gt_objs[tid*4+2], gh = gt_objs[tid*4+3];
        sGt[tid] = make_float4(gx - 0.5f*gw, gy - 0.5f*gh, gx + 0.5f*gw, gy + 0.5f*gh);
        sGtCls[tid] = gt_cls[tid];
    }
    __syncthreads();

    for (int base = 0; base < NANCH; base += CHUNK) {
        int pos = base + tid;
        unsigned int key = keysS[pos];
        bool cand = (key != 0u);
        float4 box = make_float4(0.f, 0.f, 0.f, 0.f);
        if (cand) {
            unsigned int a = valsS[pos];
            float4 dlt = reinterpret_cast<const float4*>(deltas)[a];
            float4 anc = reinterpret_cast<const float4*>(anchors)[a];
            float cx = dlt.x * anc.z + anc.x;
            float cy = dlt.y * anc.w + anc.y;
            float w  = expf(dlt.z) * anc.z;
            float h  = expf(dlt.w) * anc.w;
            box = make_float4(cx - 0.5f*w, cy - 0.5f*h, cx + 0.5f*w, cy + 0.5f*h);
        }
        sBox[tid] = box;
        if (tid == 0) sStop = (key == 0u) ? 1 : 0;   // chunk head invalid -> everything after is too

        // pre-filter against already-accepted boxes (from earlier chunks)
        int nAcc = sNAcc;
        bool alive = cand;
        for (int k = 0; k < nAcc && alive; ++k) {
            float4 ab = sAccBox[k];
            if (iou_mm(box.x, box.y, box.z, box.w, ab.x, ab.y, ab.z, ab.w) > NMS_THR)
                alive = false;
        }
        sValid[tid] = alive ? 1 : 0;
        __syncthreads();
        if (sStop) break;

        // build triangular suppression mask: bit i of row tid set if cand_i suppresses cand_tid
        {
            float4 me = box;
            #pragma unroll
            for (int w = 0; w < CHUNK/64; ++w) {
                unsigned long long m = 0ull;
                if (alive) {
                    int lim = tid - (w << 6);
                    if (lim > 64) lim = 64;
                    for (int b = 0; b < lim; ++b) {
                        int i = (w << 6) + b;
                        if (sValid[i]) {
                            float4 ob = sBox[i];
                            if (iou_mm(me.x, me.y, me.z, me.w, ob.x, ob.y, ob.z, ob.w) > NMS_THR)
                                m |= (1ull << b);
                        }
                    }
                }
                sMask[tid][w] = m;
            }
        }
        __syncthreads();

        // serial scan by warp 0: alive-set bitmask, accept in order
        if (tid < 32) {
            const int lane = tid;
            unsigned long long aliveW = 0ull;   // lane<8 owns 64-bit word `lane`
            int cnt = sNAcc;
            for (int j = 0; j < CHUNK && cnt < MAXACC; ++j) {
                if (!sValid[j]) continue;
                unsigned long long m = (lane < (CHUNK/64)) ? (sMask[j][lane] & aliveW) : 0ull;
                if (!__any_sync(0xffffffffu, m != 0ull)) {
                    if (lane == (j >> 6)) aliveW |= (1ull << (j & 63));
                    if (lane == 0) {
                        g_selPos[cnt] = (unsigned int)(base + j);
                        sAccBox[cnt] = sBox[j];
                    }
                    ++cnt;
                }
            }
            if (lane == 0) sNAcc = cnt;
        }
        __syncthreads();
        if (sNAcc >= MAXACC) break;
    }

    __syncthreads();
    const int nAcc = sNAcc;

    // ---------------- outputs: confs[300], yxminmax[300,4], cls[300] ----------------
    for (int k = tid; k < MAXACC; k += blockDim.x) {
        if (k < nAcc) {
            unsigned int pos = g_selPos[k];
            float conf = __uint_as_float(keysS[pos] + 0x3F000000u);
            float4 b = sAccBox[k];
            out[k] = conf;
            out[MAXACC + 4*k + 0] = b.y;   // ymin
            out[MAXACC + 4*k + 1] = b.x;   // xmin
            out[MAXACC + 4*k + 2] = b.w;   // ymax
            out[MAXACC + 4*k + 3] = b.z;   // xmax
            // GT assignment for this anchor only
            float best = -1.0f; int bi = 0;
            #pragma unroll 4
            for (int g = 0; g < NGT; ++g) {
                float4 gb = sGt[g];
                float v = iou_mm(b.x, b.y, b.z, b.w, gb.x, gb.y, gb.z, gb.w);
                if (v > best) { best = v; bi = g; }
            }
            out[MAXACC*5 + k] = (best < BG_THR) ? NUM_CLASSES : sGtCls[bi];
        } else {
            out[k] = 0.0f;
            out[MAXACC + 4*k + 0] = 0.0f;
            out[MAXACC + 4*k + 1] = 0.0f;
            out[MAXACC + 4*k + 2] = 0.0f;
            out[MAXACC + 4*k + 3] = 0.0f;
            out[MAXACC*5 + k] = NUM_CLASSES;
        }
    }
}

// ---------------- host launcher ----------------
extern "C" void kernel_launch(void* const* d_in, const int* in_sizes, int n_in,
                              void* d_out, int out_size) {
    const float* confs   = (const float*)d_in[0];
    const float* deltas  = (const float*)d_in[1];
    const float* anchors = (const float*)d_in[2];
    const float* gts     = (const float*)d_in[3];
    const float* gtc     = (const float*)d_in[4];
    float* out = (float*)d_out;

    unsigned int *keys, *vals, *keysS, *valsS;
    void* cub_tmp;
    cudaGetSymbolAddress((void**)&keys,  g_keys);
    cudaGetSymbolAddress((void**)&vals,  g_vals);
    cudaGetSymbolAddress((void**)&keysS, g_keys_s);
    cudaGetSymbolAddress((void**)&valsS, g_vals_s);
    cudaGetSymbolAddress(&cub_tmp, g_cub_tmp);

    build_keys_kernel<<<(NANCH + 255) / 256, 256>>>(confs, keys, vals);

    size_t tmp_bytes = 0;
    cub::DeviceRadixSort::SortPairsDescending(nullptr, tmp_bytes,
                                              keys, keysS, vals, valsS,
                                              NANCH, 0, 24);
    if (tmp_bytes <= (size_t)CUB_TMP_BYTES) {
        cub::DeviceRadixSort::SortPairsDescending(cub_tmp, tmp_bytes,
                                                  keys, keysS, vals, valsS,
                                                  NANCH, 0, 24);
    }

    nms_kernel<<<1, CHUNK>>>(keysS, valsS, deltas, anchors, gts, gtc, out);
}